// round 9
// baseline (speedup 1.0000x reference)
#include <cuda_runtime.h>
#include <math.h>
#include <stdint.h>

// Problem constants (fixed by setup_inputs)
#define B_  2
#define T_  2048
#define C_  1024
#define H_  16
#define D_  64
#define BT_ (B_*T_)          // 4096

// Scratch (allocation-free rule: __device__ globals)
__device__ float g_q[BT_*C_];
__device__ float g_k[BT_*C_];
__device__ float g_v[BT_*C_];
__device__ float g_attn[BT_*C_];
__device__ float g_xr[BT_*C_];      // tf32-rounded x
__device__ float g_wq[C_*C_];
__device__ float g_wk[C_*C_];
__device__ float g_wv[C_*C_];
__device__ float g_wo[C_*C_];

// ===========================================================================
// Helpers
// ===========================================================================
__device__ __forceinline__ uint32_t smem_u32(const void* p) {
    uint32_t a;
    asm("{ .reg .u64 t; cvta.to.shared.u64 t, %1; cvt.u32.u64 %0, t; }"
        : "=r"(a) : "l"(p));
    return a;
}
__device__ __forceinline__ void cp_async16(uint32_t saddr, const void* gaddr) {
    asm volatile("cp.async.ca.shared.global [%0], [%1], 16;"
                 :: "r"(saddr), "l"(gaddr) : "memory");
}
__device__ __forceinline__ void cp_commit() {
    asm volatile("cp.async.commit_group;" ::: "memory");
}
template<int N>
__device__ __forceinline__ void cp_wait() {
    asm volatile("cp.async.wait_group %0;" :: "n"(N) : "memory");
}
// tf32 mma: D = A(16x8) * B(8x8) + D   (row.col)
__device__ __forceinline__ void mma_tf32(float* c, const uint32_t* a, const uint32_t* b) {
    asm volatile(
        "mma.sync.aligned.m16n8k8.row.col.f32.tf32.tf32.f32 "
        "{%0,%1,%2,%3}, {%4,%5,%6,%7}, {%8,%9}, {%0,%1,%2,%3};"
        : "+f"(c[0]), "+f"(c[1]), "+f"(c[2]), "+f"(c[3])
        : "r"(a[0]), "r"(a[1]), "r"(a[2]), "r"(a[3]), "r"(b[0]), "r"(b[1]));
}
__device__ __forceinline__ float rtf32(float a) {
    float r;
    asm("cvt.rna.tf32.f32 %0, %1;" : "=f"(r) : "f"(a));
    return r;
}
__device__ __forceinline__ void split1(float x, uint32_t& hi, uint32_t& lo) {
    float h = rtf32(x);
    hi = __float_as_uint(h);
    lo = __float_as_uint(rtf32(x - h));
}

// ===========================================================================
// tf32 tensor-core GEMM (NT): C[m,n] = sum_k A[m,k] * W[n,k]
// CTA 128x128, K-chunk 32, 3-stage cp.async pipeline, ONE barrier per chunk.
// (validated R7/R8: 73.4-73.8us, tensor=37-38%)
// ===========================================================================
#define GK      32
#define GSTRIDE 36
#define G_TILE  (128 * GSTRIDE)
#define G_STAGE (2 * G_TILE)
#define G_SMEM  (3 * G_STAGE * (int)sizeof(float))   // 110592 B

__global__ __launch_bounds__(256, 2) void tf32_gemm(
    const float* __restrict__ A, const float* __restrict__ W,
    float* __restrict__ Cout, int M, int N, int K)
{
    extern __shared__ float sm[];
    const int tid  = threadIdx.x;
    const int lane = tid & 31;
    const int wid  = tid >> 5;
    const int wm   = wid >> 2;
    const int wn   = wid & 3;
    const int g    = lane >> 2;
    const int t    = lane & 3;
    const int row0 = blockIdx.y << 7;
    const int col0 = blockIdx.x << 7;

    float acc[4][4][4];
    #pragma unroll
    for (int i = 0; i < 4; ++i)
        #pragma unroll
        for (int j = 0; j < 4; ++j)
            #pragma unroll
            for (int r = 0; r < 4; ++r) acc[i][j][r] = 0.f;

    const int cr = tid >> 3;
    const int cc = (tid & 7) << 2;
    const int nchunk = K / GK;

    #pragma unroll
    for (int pc = 0; pc < 2; ++pc) {
        float* as = sm + pc * G_STAGE;
        float* bs = as + G_TILE;
        const int k0 = pc * GK;
        #pragma unroll
        for (int it = 0; it < 4; ++it) {
            int r = cr + (it << 5);
            cp_async16(smem_u32(as + r * GSTRIDE + cc),
                       A + (size_t)(row0 + r) * K + k0 + cc);
            cp_async16(smem_u32(bs + r * GSTRIDE + cc),
                       W + (size_t)(col0 + r) * K + k0 + cc);
        }
        cp_commit();
    }

    int buf = 0;
    int nbuf = 2;
    for (int i = 0; i < nchunk; ++i) {
        if (i + 1 < nchunk) cp_wait<1>(); else cp_wait<0>();
        __syncthreads();

        if (i + 2 < nchunk) {
            float* as = sm + nbuf * G_STAGE;
            float* bs = as + G_TILE;
            const int k0 = (i + 2) * GK;
            #pragma unroll
            for (int it = 0; it < 4; ++it) {
                int r = cr + (it << 5);
                cp_async16(smem_u32(as + r * GSTRIDE + cc),
                           A + (size_t)(row0 + r) * K + k0 + cc);
                cp_async16(smem_u32(bs + r * GSTRIDE + cc),
                           W + (size_t)(col0 + r) * K + k0 + cc);
            }
            cp_commit();
        }

        const float* as = sm + buf * G_STAGE + wm * 64 * GSTRIDE;
        const float* bs = sm + buf * G_STAGE + G_TILE + wn * 32 * GSTRIDE;

        #pragma unroll
        for (int ks = 0; ks < 4; ++ks) {
            uint32_t af[4][4];
            #pragma unroll
            for (int mt = 0; mt < 4; ++mt) {
                const uint32_t* ap =
                    (const uint32_t*)(as + (mt * 16 + g) * GSTRIDE + ks * 8 + t);
                af[mt][0] = ap[0];
                af[mt][1] = ap[8 * GSTRIDE];
                af[mt][2] = ap[4];
                af[mt][3] = ap[8 * GSTRIDE + 4];
            }
            uint32_t bf[4][2];
            #pragma unroll
            for (int nt = 0; nt < 4; ++nt) {
                const uint32_t* bp =
                    (const uint32_t*)(bs + (nt * 8 + g) * GSTRIDE + ks * 8 + t);
                bf[nt][0] = bp[0];
                bf[nt][1] = bp[4];
            }
            #pragma unroll
            for (int mt = 0; mt < 4; ++mt)
                #pragma unroll
                for (int nt = 0; nt < 4; ++nt)
                    mma_tf32(acc[mt][nt], af[mt], bf[nt]);
        }

        buf  = (buf  + 1 == 3) ? 0 : buf  + 1;
        nbuf = (nbuf + 1 == 3) ? 0 : nbuf + 1;
    }

    #pragma unroll
    for (int mt = 0; mt < 4; ++mt) {
        #pragma unroll
        for (int nt = 0; nt < 4; ++nt) {
            int row = row0 + wm * 64 + mt * 16 + g;
            int col = col0 + wn * 32 + nt * 8 + 2 * t;
            *(float2*)(Cout + (size_t)row * N + col) =
                make_float2(acc[mt][nt][0], acc[mt][nt][1]);
            *(float2*)(Cout + (size_t)(row + 8) * N + col) =
                make_float2(acc[mt][nt][2], acc[mt][nt][3]);
        }
    }
}

// ===========================================================================
// Round fp32 -> nearest-tf32 (simple per-tensor kernel, R6 style)
// ===========================================================================
__global__ void tf32_round_kernel(const float4* __restrict__ in,
                                  float4* __restrict__ out, int n4)
{
    int i = blockIdx.x * blockDim.x + threadIdx.x;
    if (i >= n4) return;
    float4 v = in[i];
    v.x = rtf32(v.x); v.y = rtf32(v.y); v.z = rtf32(v.z); v.w = rtf32(v.w);
    out[i] = v;
}

// ---------------------------------------------------------------------------
// RoPE in-place on Q and K
// ---------------------------------------------------------------------------
__global__ void rope_kernel(float* __restrict__ q, float* __restrict__ k)
{
    int idx = blockIdx.x * blockDim.x + threadIdx.x;
    int i = idx & 31;
    int h = (idx >> 5) & 15;
    int t = (idx >> 9) & 2047;
    int b = idx >> 20;

    float inv = powf(10000.0f, -(float)(2 * i) / (float)D_);
    float ang = (float)t * inv;
    float s, c;
    sincosf(ang, &s, &c);

    size_t base = ((size_t)(b * T_ + t)) * C_ + h * D_ + i;
    float x1 = q[base], x2 = q[base + 32];
    q[base]      = x1 * c - x2 * s;
    q[base + 32] = x2 * c + x1 * s;
    x1 = k[base]; x2 = k[base + 32];
    k[base]      = x1 * c - x2 * s;
    k[base + 32] = x2 * c + x1 * s;
}

// ===========================================================================
// Tensor-core causal flash attention, R9:
//  - K and V pre-split ONCE per CTA into hi/lo-interleaved smem (stride 136):
//    fragment loads become single LDS.64, zero split ALU in MMA loops.
//  - QK = tf32x3 (Q split in-loop: 4 elems/lane/ks).
//  - PV = 2 MMAs: P stored tf32-rounded, O += P*(Vhi + Vlo).
//  - P overwrites the K smem region after QK (same 8704-float footprint).
// Tile 128 queries x 64 keys, 256 threads, warp w owns 16 query rows.
// ===========================================================================
#define FQ    128
#define FK    64
#define QSTR  68            // 4g+t distinct mod 32 for LDS.32
#define HLSTR 136           // == 8 mod 32 -> LDS.64 conflict-free both patterns
#define PSTR  68
#define FA_Q  0
#define FA_K  (FQ*QSTR)               // 8704 floats
#define FA_V  (FA_K + FK*HLSTR)       // 17408
#define FA_SMEM ((FA_V + FK*HLSTR) * (int)sizeof(float))   // 104448 B

__global__ __launch_bounds__(256, 2) void flash_attn_tc(
    const float* __restrict__ q, const float* __restrict__ k,
    const float* __restrict__ v, float* __restrict__ o)
{
    extern __shared__ float sm[];
    float* Qs  = sm + FA_Q;
    float* Khl = sm + FA_K;
    float* Vhl = sm + FA_V;
    float* Ps  = sm + FA_K;            // P aliases K after QK

    const int tid  = threadIdx.x;
    const int lane = tid & 31;
    const int w    = tid >> 5;
    const int g    = lane >> 2;
    const int t    = lane & 3;
    const int qb   = blockIdx.x;
    const int bh   = blockIdx.y;
    const int b    = bh >> 4, h = bh & 15;
    const int i0   = qb << 7;

    const float* qbp = q + (size_t)b * T_ * C_ + h * D_;
    const float* kbp = k + (size_t)b * T_ * C_ + h * D_;
    const float* vbp = v + (size_t)b * T_ * C_ + h * D_;

    // Q tile (128 x 64, fp32) via cp.async
    #pragma unroll
    for (int it = 0; it < 8; ++it) {
        int task = tid + (it << 8);
        int r = task >> 4, c = (task & 15) << 2;
        cp_async16(smem_u32(Qs + r * QSTR + c),
                   qbp + (size_t)(i0 + r) * C_ + c);
    }
    cp_commit();

    float oacc[8][4];
    #pragma unroll
    for (int nt = 0; nt < 8; ++nt)
        #pragma unroll
        for (int e = 0; e < 4; ++e) oacc[nt][e] = 0.f;
    float m0 = -1e30f, m1 = -1e30f, l0 = 0.f, l1 = 0.f;

    const int grow0 = i0 + w * 16 + g;
    const int njt = (i0 >> 6) + 2;

    for (int j = 0; j < njt; ++j) {
        __syncthreads();                 // all warps done with prev P(=K)/V

        // ---- load + split K, V into hi/lo-interleaved smem ----
        #pragma unroll
        for (int it = 0; it < 4; ++it) {
            int task = tid + (it << 8);
            int r = task >> 4;           // 0..63
            int c = (task & 15) << 2;    // 0..60
            float4 kv = *(const float4*)(kbp + (size_t)((j << 6) + r) * C_ + c);
            float4 vv = *(const float4*)(vbp + (size_t)((j << 6) + r) * C_ + c);
            float kh0 = rtf32(kv.x), kh1 = rtf32(kv.y);
            float kh2 = rtf32(kv.z), kh3 = rtf32(kv.w);
            *(float4*)(Khl + r * HLSTR + 2 * c) =
                make_float4(kh0, rtf32(kv.x - kh0), kh1, rtf32(kv.y - kh1));
            *(float4*)(Khl + r * HLSTR + 2 * c + 4) =
                make_float4(kh2, rtf32(kv.z - kh2), kh3, rtf32(kv.w - kh3));
            float vh0 = rtf32(vv.x), vh1 = rtf32(vv.y);
            float vh2 = rtf32(vv.z), vh3 = rtf32(vv.w);
            *(float4*)(Vhl + r * HLSTR + 2 * c) =
                make_float4(vh0, rtf32(vv.x - vh0), vh1, rtf32(vv.y - vh1));
            *(float4*)(Vhl + r * HLSTR + 2 * c + 4) =
                make_float4(vh2, rtf32(vv.z - vh2), vh3, rtf32(vv.w - vh3));
        }
        cp_wait<0>();                    // Q resident (no-op after j==0)
        __syncthreads();

        // ---- S = Q K^T  (tf32x3; K pre-split) ----
        float sacc[8][4];
        #pragma unroll
        for (int nt = 0; nt < 8; ++nt)
            #pragma unroll
            for (int e = 0; e < 4; ++e) sacc[nt][e] = 0.f;

        const float* qrow = Qs + (w * 16 + g) * QSTR;
        #pragma unroll
        for (int ks = 0; ks < 8; ++ks) {
            uint32_t ah[4], al[4];
            split1(qrow[ks * 8 + t],                ah[0], al[0]);
            split1(qrow[8 * QSTR + ks * 8 + t],     ah[1], al[1]);
            split1(qrow[ks * 8 + t + 4],            ah[2], al[2]);
            split1(qrow[8 * QSTR + ks * 8 + t + 4], ah[3], al[3]);
            #pragma unroll
            for (int nt = 0; nt < 8; ++nt) {
                const float2* kp2 = (const float2*)(Khl + (nt * 8 + g) * HLSTR);
                float2 p0 = kp2[ks * 8 + t];
                float2 p1 = kp2[ks * 8 + t + 4];
                uint32_t bh2[2] = { __float_as_uint(p0.x), __float_as_uint(p1.x) };
                uint32_t bl2[2] = { __float_as_uint(p0.y), __float_as_uint(p1.y) };
                mma_tf32(sacc[nt], ah, bh2);
                mma_tf32(sacc[nt], ah, bl2);
                mma_tf32(sacc[nt], al, bh2);
            }
        }

        // ---- online softmax ----
        const int colj = j << 6;
        float mx0 = -1e30f, mx1 = -1e30f;
        #pragma unroll
        for (int nt = 0; nt < 8; ++nt) {
            #pragma unroll
            for (int e = 0; e < 4; ++e) {
                int gcol = colj + nt * 8 + 2 * t + (e & 1);
                int grow = (e < 2) ? grow0 : grow0 + 8;
                float val = sacc[nt][e] * 0.125f;
                if (gcol > grow) val = -1e30f;
                sacc[nt][e] = val;
            }
            mx0 = fmaxf(mx0, fmaxf(sacc[nt][0], sacc[nt][1]));
            mx1 = fmaxf(mx1, fmaxf(sacc[nt][2], sacc[nt][3]));
        }
        mx0 = fmaxf(mx0, __shfl_xor_sync(0xffffffffu, mx0, 1));
        mx0 = fmaxf(mx0, __shfl_xor_sync(0xffffffffu, mx0, 2));
        mx1 = fmaxf(mx1, __shfl_xor_sync(0xffffffffu, mx1, 1));
        mx1 = fmaxf(mx1, __shfl_xor_sync(0xffffffffu, mx1, 2));

        float mn0 = fmaxf(m0, mx0), mn1 = fmaxf(m1, mx1);
        float sc0 = __expf(m0 - mn0), sc1 = __expf(m1 - mn1);
        float rs0 = 0.f, rs1 = 0.f;
        #pragma unroll
        for (int nt = 0; nt < 8; ++nt) {
            float p0 = __expf(sacc[nt][0] - mn0);
            float p1 = __expf(sacc[nt][1] - mn0);
            float p2 = __expf(sacc[nt][2] - mn1);
            float p3 = __expf(sacc[nt][3] - mn1);
            sacc[nt][0] = p0; sacc[nt][1] = p1;
            sacc[nt][2] = p2; sacc[nt][3] = p3;
            rs0 += p0 + p1; rs1 += p2 + p3;
        }
        rs0 += __shfl_xor_sync(0xffffffffu, rs0, 1);
        rs0 += __shfl_xor_sync(0xffffffffu, rs0, 2);
        rs1 += __shfl_xor_sync(0xffffffffu, rs1, 1);
        rs1 += __shfl_xor_sync(0xffffffffu, rs1, 2);
        l0 = l0 * sc0 + rs0; m0 = mn0;
        l1 = l1 * sc1 + rs1; m1 = mn1;
        #pragma unroll
        for (int nt = 0; nt < 8; ++nt) {
            oacc[nt][0] *= sc0; oacc[nt][1] *= sc0;
            oacc[nt][2] *= sc1; oacc[nt][3] *= sc1;
        }

        // ---- write P (tf32-rounded) into the K region ----
        __syncthreads();                 // all warps done reading K
        float* prow = Ps + (w * 16 + g) * PSTR;
        #pragma unroll
        for (int nt = 0; nt < 8; ++nt) {
            *(float2*)(prow + nt * 8 + 2 * t) =
                make_float2(rtf32(sacc[nt][0]), rtf32(sacc[nt][1]));
            *(float2*)(prow + 8 * PSTR + nt * 8 + 2 * t) =
                make_float2(rtf32(sacc[nt][2]), rtf32(sacc[nt][3]));
        }
        __syncwarp();                    // warp-private rows visible

        // ---- O += P * (Vhi + Vlo)  (2 MMAs) ----
        #pragma unroll
        for (int ks = 0; ks < 8; ++ks) {
            uint32_t ap[4] = {
                __float_as_uint(prow[ks * 8 + t]),
                __float_as_uint(prow[8 * PSTR + ks * 8 + t]),
                __float_as_uint(prow[ks * 8 + t + 4]),
                __float_as_uint(prow[8 * PSTR + ks * 8 + t + 4]) };
            #pragma unroll
            for (int nt = 0; nt < 8; ++nt) {
                const float2* vp0 = (const float2*)(Vhl + (ks * 8 + t) * HLSTR);
                const float2* vp1 = (const float2*)(Vhl + (ks * 8 + t + 4) * HLSTR);
                float2 v0 = vp0[nt * 8 + g];
                float2 v1 = vp1[nt * 8 + g];
                uint32_t bh2[2] = { __float_as_uint(v0.x), __float_as_uint(v1.x) };
                uint32_t bl2[2] = { __float_as_uint(v0.y), __float_as_uint(v1.y) };
                mma_tf32(oacc[nt], ap, bh2);
                mma_tf32(oacc[nt], ap, bl2);
            }
        }
    }

    // ---- epilogue (pre-rounded to tf32 for the Wo GEMM) ----
    float iv0 = 1.f / l0, iv1 = 1.f / l1;
    float* ob = o + (size_t)b * T_ * C_ + h * D_;
    #pragma unroll
    for (int nt = 0; nt < 8; ++nt) {
        int col = nt * 8 + 2 * t;
        *(float2*)(ob + (size_t)grow0 * C_ + col) =
            make_float2(rtf32(oacc[nt][0] * iv0), rtf32(oacc[nt][1] * iv0));
        *(float2*)(ob + (size_t)(grow0 + 8) * C_ + col) =
            make_float2(rtf32(oacc[nt][2] * iv1), rtf32(oacc[nt][3] * iv1));
    }
}

// ---------------------------------------------------------------------------
// Launch
// ---------------------------------------------------------------------------
extern "C" void kernel_launch(void* const* d_in, const int* in_sizes, int n_in,
                              void* d_out, int out_size)
{
    const float* x  = (const float*)d_in[0];
    const float* Wq = (const float*)d_in[1];
    const float* Wk = (const float*)d_in[2];
    const float* Wv = (const float*)d_in[3];
    const float* Wo = (const float*)d_in[4];
    float* out = (float*)d_out;

    float *qp, *kp, *vp, *ap, *xr, *wq, *wk, *wv, *wo;
    cudaGetSymbolAddress((void**)&qp, g_q);
    cudaGetSymbolAddress((void**)&kp, g_k);
    cudaGetSymbolAddress((void**)&vp, g_v);
    cudaGetSymbolAddress((void**)&ap, g_attn);
    cudaGetSymbolAddress((void**)&xr, g_xr);
    cudaGetSymbolAddress((void**)&wq, g_wq);
    cudaGetSymbolAddress((void**)&wk, g_wk);
    cudaGetSymbolAddress((void**)&wv, g_wv);
    cudaGetSymbolAddress((void**)&wo, g_wo);

    cudaFuncSetAttribute((const void*)tf32_gemm,
                         cudaFuncAttributeMaxDynamicSharedMemorySize, G_SMEM);
    cudaFuncSetAttribute((const void*)flash_attn_tc,
                         cudaFuncAttributeMaxDynamicSharedMemorySize, FA_SMEM);

    // Round GEMM operands to nearest-tf32 (simple kernels, R6 style)
    int n4x = BT_ * C_ / 4, n4w = C_ * C_ / 4;
    tf32_round_kernel<<<n4x / 256, 256>>>((const float4*)x,  (float4*)xr, n4x);
    tf32_round_kernel<<<n4w / 256, 256>>>((const float4*)Wq, (float4*)wq, n4w);
    tf32_round_kernel<<<n4w / 256, 256>>>((const float4*)Wk, (float4*)wk, n4w);
    tf32_round_kernel<<<n4w / 256, 256>>>((const float4*)Wv, (float4*)wv, n4w);
    tf32_round_kernel<<<n4w / 256, 256>>>((const float4*)Wo, (float4*)wo, n4w);

    dim3 gg(C_ / 128, BT_ / 128);   // (8, 32)
    tf32_gemm<<<gg, 256, G_SMEM>>>(xr, wq, qp, BT_, C_, C_);
    tf32_gemm<<<gg, 256, G_SMEM>>>(xr, wk, kp, BT_, C_, C_);
    tf32_gemm<<<gg, 256, G_SMEM>>>(xr, wv, vp, BT_, C_, C_);

    rope_kernel<<<(B_ * T_ * H_ * (D_ / 2)) / 256, 256>>>(qp, kp);

    flash_attn_tc<<<dim3(T_ / 128, B_ * H_), 256, FA_SMEM>>>(qp, kp, vp, ap);

    tf32_gemm<<<gg, 256, G_SMEM>>>(ap, wo, out, BT_, C_, C_);
}

// round 12
// speedup vs baseline: 2.0209x; 2.0209x over previous
#include <cuda_runtime.h>
#include <math.h>
#include <stdint.h>

// Problem constants (fixed by setup_inputs)
#define B_  2
#define T_  2048
#define C_  1024
#define H_  16
#define D_  64
#define BT_ (B_*T_)          // 4096

// Scratch (allocation-free rule: __device__ globals)
__device__ float g_q[BT_*C_];
__device__ float g_k[BT_*C_];
__device__ float g_v[BT_*C_];
__device__ float g_attn[BT_*C_];
__device__ float g_xr[BT_*C_];      // tf32-rounded x
__device__ float g_wq[C_*C_];
__device__ float g_wk[C_*C_];
__device__ float g_wv[C_*C_];
__device__ float g_wo[C_*C_];

// ===========================================================================
// Helpers
// ===========================================================================
__device__ __forceinline__ uint32_t smem_u32(const void* p) {
    uint32_t a;
    asm("{ .reg .u64 t; cvta.to.shared.u64 t, %1; cvt.u32.u64 %0, t; }"
        : "=r"(a) : "l"(p));
    return a;
}
__device__ __forceinline__ void cp_async16(uint32_t saddr, const void* gaddr) {
    asm volatile("cp.async.ca.shared.global [%0], [%1], 16;"
                 :: "r"(saddr), "l"(gaddr) : "memory");
}
__device__ __forceinline__ void cp_commit() {
    asm volatile("cp.async.commit_group;" ::: "memory");
}
template<int N>
__device__ __forceinline__ void cp_wait() {
    asm volatile("cp.async.wait_group %0;" :: "n"(N) : "memory");
}
// tf32 mma: D = A(16x8) * B(8x8) + D   (row.col)
__device__ __forceinline__ void mma_tf32(float* c, const uint32_t* a, const uint32_t* b) {
    asm volatile(
        "mma.sync.aligned.m16n8k8.row.col.f32.tf32.tf32.f32 "
        "{%0,%1,%2,%3}, {%4,%5,%6,%7}, {%8,%9}, {%0,%1,%2,%3};"
        : "+f"(c[0]), "+f"(c[1]), "+f"(c[2]), "+f"(c[3])
        : "r"(a[0]), "r"(a[1]), "r"(a[2]), "r"(a[3]), "r"(b[0]), "r"(b[1]));
}
__device__ __forceinline__ float rtf32(float a) {
    float r;
    asm("cvt.rna.tf32.f32 %0, %1;" : "=f"(r) : "f"(a));
    return r;
}
__device__ __forceinline__ void split1(float x, uint32_t& hi, uint32_t& lo) {
    float h = rtf32(x);
    hi = __float_as_uint(h);
    lo = __float_as_uint(rtf32(x - h));
}

// ===========================================================================
// tf32 tensor-core GEMM (NT): C[m,n] = sum_k A[m,k] * W[n,k]
// CTA 128x128, K-chunk 32, 2-stage cp.async pipeline (R6-measured config).
// round_out != 0 -> epilogue rounds results to nearest-tf32 (for V).
// ===========================================================================
#define GK      32
#define GSTRIDE 36
#define G_TILE  (128 * GSTRIDE)
#define G_STAGE (2 * G_TILE)
#define G_SMEM  (2 * G_STAGE * (int)sizeof(float))   // 73728 B

__global__ __launch_bounds__(256, 2) void tf32_gemm(
    const float* __restrict__ A, const float* __restrict__ W,
    float* __restrict__ Cout, int M, int N, int K, int round_out)
{
    extern __shared__ float sm[];
    const int tid  = threadIdx.x;
    const int lane = tid & 31;
    const int wid  = tid >> 5;
    const int wm   = wid >> 2;
    const int wn   = wid & 3;
    const int g    = lane >> 2;
    const int t    = lane & 3;
    const int row0 = blockIdx.y << 7;
    const int col0 = blockIdx.x << 7;

    float acc[4][4][4];
    #pragma unroll
    for (int i = 0; i < 4; ++i)
        #pragma unroll
        for (int j = 0; j < 4; ++j)
            #pragma unroll
            for (int r = 0; r < 4; ++r) acc[i][j][r] = 0.f;

    const int cr = tid >> 3;
    const int cc = (tid & 7) << 2;
    const int nchunk = K / GK;

    {
        float* as = sm;
        float* bs = sm + G_TILE;
        #pragma unroll
        for (int it = 0; it < 4; ++it) {
            int r = cr + (it << 5);
            cp_async16(smem_u32(as + r * GSTRIDE + cc),
                       A + (size_t)(row0 + r) * K + cc);
            cp_async16(smem_u32(bs + r * GSTRIDE + cc),
                       W + (size_t)(col0 + r) * K + cc);
        }
        cp_commit();
    }

    for (int i = 0; i < nchunk; ++i) {
        if (i + 1 < nchunk) {
            float* as = sm + ((i + 1) & 1) * G_STAGE;
            float* bs = as + G_TILE;
            const int k0 = (i + 1) * GK;
            #pragma unroll
            for (int it = 0; it < 4; ++it) {
                int r = cr + (it << 5);
                cp_async16(smem_u32(as + r * GSTRIDE + cc),
                           A + (size_t)(row0 + r) * K + k0 + cc);
                cp_async16(smem_u32(bs + r * GSTRIDE + cc),
                           W + (size_t)(col0 + r) * K + k0 + cc);
            }
            cp_commit();
            cp_wait<1>();
        } else {
            cp_wait<0>();
        }
        __syncthreads();

        const float* as = sm + (i & 1) * G_STAGE + wm * 64 * GSTRIDE;
        const float* bs = sm + (i & 1) * G_STAGE + G_TILE + wn * 32 * GSTRIDE;

        #pragma unroll
        for (int ks = 0; ks < 4; ++ks) {
            uint32_t af[4][4];
            #pragma unroll
            for (int mt = 0; mt < 4; ++mt) {
                const uint32_t* ap =
                    (const uint32_t*)(as + (mt * 16 + g) * GSTRIDE + ks * 8 + t);
                af[mt][0] = ap[0];
                af[mt][1] = ap[8 * GSTRIDE];
                af[mt][2] = ap[4];
                af[mt][3] = ap[8 * GSTRIDE + 4];
            }
            uint32_t bf[4][2];
            #pragma unroll
            for (int nt = 0; nt < 4; ++nt) {
                const uint32_t* bp =
                    (const uint32_t*)(bs + (nt * 8 + g) * GSTRIDE + ks * 8 + t);
                bf[nt][0] = bp[0];
                bf[nt][1] = bp[4];
            }
            #pragma unroll
            for (int mt = 0; mt < 4; ++mt)
                #pragma unroll
                for (int nt = 0; nt < 4; ++nt)
                    mma_tf32(acc[mt][nt], af[mt], bf[nt]);
        }
        __syncthreads();
    }

    #pragma unroll
    for (int mt = 0; mt < 4; ++mt) {
        #pragma unroll
        for (int nt = 0; nt < 4; ++nt) {
            int row = row0 + wm * 64 + mt * 16 + g;
            int col = col0 + wn * 32 + nt * 8 + 2 * t;
            float c0 = acc[mt][nt][0], c1 = acc[mt][nt][1];
            float c2 = acc[mt][nt][2], c3 = acc[mt][nt][3];
            if (round_out) {
                c0 = rtf32(c0); c1 = rtf32(c1);
                c2 = rtf32(c2); c3 = rtf32(c3);
            }
            *(float2*)(Cout + (size_t)row * N + col) = make_float2(c0, c1);
            *(float2*)(Cout + (size_t)(row + 8) * N + col) = make_float2(c2, c3);
        }
    }
}

// ===========================================================================
// Round fp32 -> nearest-tf32 (simple per-tensor kernel, R6 style)
// ===========================================================================
__global__ void tf32_round_kernel(const float4* __restrict__ in,
                                  float4* __restrict__ out, int n4)
{
    int i = blockIdx.x * blockDim.x + threadIdx.x;
    if (i >= n4) return;
    float4 v = in[i];
    v.x = rtf32(v.x); v.y = rtf32(v.y); v.z = rtf32(v.z); v.w = rtf32(v.w);
    out[i] = v;
}

// ---------------------------------------------------------------------------
// RoPE in-place on Q and K. K output is tf32-rounded (flash uses K raw
// in single-MMA-precision position; Q stays fp32 and is hi/lo split there).
// ---------------------------------------------------------------------------
__global__ void rope_kernel(float* __restrict__ q, float* __restrict__ k)
{
    int idx = blockIdx.x * blockDim.x + threadIdx.x;
    int i = idx & 31;
    int h = (idx >> 5) & 15;
    int t = (idx >> 9) & 2047;
    int b = idx >> 20;

    float inv = powf(10000.0f, -(float)(2 * i) / (float)D_);
    float ang = (float)t * inv;
    float s, c;
    sincosf(ang, &s, &c);

    size_t base = ((size_t)(b * T_ + t)) * C_ + h * D_ + i;
    float x1 = q[base], x2 = q[base + 32];
    q[base]      = x1 * c - x2 * s;
    q[base + 32] = x2 * c + x1 * s;
    x1 = k[base]; x2 = k[base + 32];
    k[base]      = rtf32(x1 * c - x2 * s);
    k[base + 32] = rtf32(x2 * c + x1 * s);
}

// ===========================================================================
// Tensor-core causal flash attention, R10 (R6 skeleton, halved MMA count):
//  - K pre-rounded tf32 (by rope), V pre-rounded tf32 (by Wv GEMM epilogue)
//  - QK: (q_hi + q_lo) * K  -> 2 MMAs, no in-loop K splits
//  - PV: P_rna * V          -> 1 MMA,  no in-loop splits at all
//  - identical smem layout / cp.async loads / sync structure to R6 (826.5us)
// Tile 128 queries x 64 keys, 256 threads, warp w owns 16 query rows.
// ===========================================================================
#define FQ   128
#define FK   64
#define QSTR 68
#define KSTR 68
#define VSTR 72
#define PSTR 68
#define FA2_Q 0
#define FA2_K (FQ*QSTR)                       // 8704
#define FA2_V (FA2_K + FK*KSTR)               // 13056
#define FA2_P (FA2_V + FK*VSTR)               // 17664
#define FA2_SMEM ((FA2_P + FQ*PSTR) * (int)sizeof(float))   // 105472 B

__global__ __launch_bounds__(256) void flash_attn_tc(
    const float* __restrict__ q, const float* __restrict__ k,
    const float* __restrict__ v, float* __restrict__ o)
{
    extern __shared__ float sm[];
    float* Qs = sm + FA2_Q;
    float* Ks = sm + FA2_K;
    float* Vs = sm + FA2_V;
    float* Ps = sm + FA2_P;

    const int tid  = threadIdx.x;
    const int lane = tid & 31;
    const int w    = tid >> 5;
    const int g    = lane >> 2;
    const int t    = lane & 3;
    const int qb   = blockIdx.x;
    const int bh   = blockIdx.y;
    const int b    = bh >> 4, h = bh & 15;
    const int i0   = qb << 7;

    const float* qbp = q + (size_t)b * T_ * C_ + h * D_;
    const float* kbp = k + (size_t)b * T_ * C_ + h * D_;
    const float* vbp = v + (size_t)b * T_ * C_ + h * D_;

    // Load Q tile (128 x 64) via cp.async
    #pragma unroll
    for (int it = 0; it < 8; ++it) {
        int task = tid + (it << 8);
        int r = task >> 4, c = (task & 15) << 2;
        cp_async16(smem_u32(Qs + r * QSTR + c),
                   qbp + (size_t)(i0 + r) * C_ + c);
    }
    cp_commit();

    float oacc[8][4];
    #pragma unroll
    for (int nt = 0; nt < 8; ++nt)
        #pragma unroll
        for (int e = 0; e < 4; ++e) oacc[nt][e] = 0.f;
    float m0 = -1e30f, m1 = -1e30f, l0 = 0.f, l1 = 0.f;

    const int grow0 = i0 + w * 16 + g;
    const int njt = (i0 >> 6) + 2;          // causal key-tile count

    for (int j = 0; j < njt; ++j) {
        __syncthreads();                    // prev iter done reading K/V
        #pragma unroll
        for (int it = 0; it < 4; ++it) {
            int task = tid + (it << 8);
            int r = task >> 4, c = (task & 15) << 2;
            cp_async16(smem_u32(Ks + r * KSTR + c),
                       kbp + (size_t)((j << 6) + r) * C_ + c);
            cp_async16(smem_u32(Vs + r * VSTR + c),
                       vbp + (size_t)((j << 6) + r) * C_ + c);
        }
        cp_commit();
        cp_wait<0>();
        __syncthreads();

        // ---- S = (Q_hi + Q_lo) K^T  (2 MMAs; K already tf32-exact) ----
        float sacc[8][4];
        #pragma unroll
        for (int nt = 0; nt < 8; ++nt)
            #pragma unroll
            for (int e = 0; e < 4; ++e) sacc[nt][e] = 0.f;

        const float* qrow = Qs + (w * 16 + g) * QSTR;
        #pragma unroll
        for (int ks = 0; ks < 8; ++ks) {
            uint32_t ah[4], al[4];
            split1(qrow[ks * 8 + t],                ah[0], al[0]);
            split1(qrow[8 * QSTR + ks * 8 + t],     ah[1], al[1]);
            split1(qrow[ks * 8 + t + 4],            ah[2], al[2]);
            split1(qrow[8 * QSTR + ks * 8 + t + 4], ah[3], al[3]);
            #pragma unroll
            for (int nt = 0; nt < 8; ++nt) {
                const uint32_t* krow =
                    (const uint32_t*)(Ks + (nt * 8 + g) * KSTR + ks * 8);
                uint32_t bf[2] = { krow[t], krow[t + 4] };
                mma_tf32(sacc[nt], ah, bf);
                mma_tf32(sacc[nt], al, bf);
            }
        }

        // ---- online softmax ----
        const int colj = j << 6;
        float mx0 = -1e30f, mx1 = -1e30f;
        #pragma unroll
        for (int nt = 0; nt < 8; ++nt) {
            #pragma unroll
            for (int e = 0; e < 4; ++e) {
                int gcol = colj + nt * 8 + 2 * t + (e & 1);
                int grow = (e < 2) ? grow0 : grow0 + 8;
                float val = sacc[nt][e] * 0.125f;
                if (gcol > grow) val = -1e30f;
                sacc[nt][e] = val;
            }
            mx0 = fmaxf(mx0, fmaxf(sacc[nt][0], sacc[nt][1]));
            mx1 = fmaxf(mx1, fmaxf(sacc[nt][2], sacc[nt][3]));
        }
        mx0 = fmaxf(mx0, __shfl_xor_sync(0xffffffffu, mx0, 1));
        mx0 = fmaxf(mx0, __shfl_xor_sync(0xffffffffu, mx0, 2));
        mx1 = fmaxf(mx1, __shfl_xor_sync(0xffffffffu, mx1, 1));
        mx1 = fmaxf(mx1, __shfl_xor_sync(0xffffffffu, mx1, 2));

        float mn0 = fmaxf(m0, mx0), mn1 = fmaxf(m1, mx1);
        float sc0 = __expf(m0 - mn0), sc1 = __expf(m1 - mn1);
        float rs0 = 0.f, rs1 = 0.f;
        #pragma unroll
        for (int nt = 0; nt < 8; ++nt) {
            float p0 = __expf(sacc[nt][0] - mn0);
            float p1 = __expf(sacc[nt][1] - mn0);
            float p2 = __expf(sacc[nt][2] - mn1);
            float p3 = __expf(sacc[nt][3] - mn1);
            sacc[nt][0] = p0; sacc[nt][1] = p1;
            sacc[nt][2] = p2; sacc[nt][3] = p3;
            rs0 += p0 + p1; rs1 += p2 + p3;
        }
        rs0 += __shfl_xor_sync(0xffffffffu, rs0, 1);
        rs0 += __shfl_xor_sync(0xffffffffu, rs0, 2);
        rs1 += __shfl_xor_sync(0xffffffffu, rs1, 1);
        rs1 += __shfl_xor_sync(0xffffffffu, rs1, 2);
        l0 = l0 * sc0 + rs0; m0 = mn0;
        l1 = l1 * sc1 + rs1; m1 = mn1;
        #pragma unroll
        for (int nt = 0; nt < 8; ++nt) {
            oacc[nt][0] *= sc0; oacc[nt][1] *= sc0;
            oacc[nt][2] *= sc1; oacc[nt][3] *= sc1;
        }

        // ---- write P (tf32-rounded, warp-private rows) ----
        __syncwarp();
        float* prow = Ps + (w * 16 + g) * PSTR;
        #pragma unroll
        for (int nt = 0; nt < 8; ++nt) {
            *(float2*)(prow + nt * 8 + 2 * t) =
                make_float2(rtf32(sacc[nt][0]), rtf32(sacc[nt][1]));
            *(float2*)(prow + 8 * PSTR + nt * 8 + 2 * t) =
                make_float2(rtf32(sacc[nt][2]), rtf32(sacc[nt][3]));
        }
        __syncwarp();

        // ---- O += P V  (1 MMA; P and V both tf32-exact) ----
        #pragma unroll
        for (int ks = 0; ks < 8; ++ks) {
            uint32_t ap[4] = {
                __float_as_uint(prow[ks * 8 + t]),
                __float_as_uint(prow[8 * PSTR + ks * 8 + t]),
                __float_as_uint(prow[ks * 8 + t + 4]),
                __float_as_uint(prow[8 * PSTR + ks * 8 + t + 4]) };
            #pragma unroll
            for (int nt = 0; nt < 8; ++nt) {
                uint32_t bf[2] = {
                    __float_as_uint(Vs[(ks * 8 + t) * VSTR + nt * 8 + g]),
                    __float_as_uint(Vs[(ks * 8 + t + 4) * VSTR + nt * 8 + g]) };
                mma_tf32(oacc[nt], ap, bf);
            }
        }
    }

    // ---- epilogue (pre-rounded to tf32 for the Wo GEMM) ----
    float iv0 = 1.f / l0, iv1 = 1.f / l1;
    float* ob = o + (size_t)b * T_ * C_ + h * D_;
    #pragma unroll
    for (int nt = 0; nt < 8; ++nt) {
        int col = nt * 8 + 2 * t;
        *(float2*)(ob + (size_t)grow0 * C_ + col) =
            make_float2(rtf32(oacc[nt][0] * iv0), rtf32(oacc[nt][1] * iv0));
        *(float2*)(ob + (size_t)(grow0 + 8) * C_ + col) =
            make_float2(rtf32(oacc[nt][2] * iv1), rtf32(oacc[nt][3] * iv1));
    }
}

// ---------------------------------------------------------------------------
// Launch
// ---------------------------------------------------------------------------
extern "C" void kernel_launch(void* const* d_in, const int* in_sizes, int n_in,
                              void* d_out, int out_size)
{
    const float* x  = (const float*)d_in[0];
    const float* Wq = (const float*)d_in[1];
    const float* Wk = (const float*)d_in[2];
    const float* Wv = (const float*)d_in[3];
    const float* Wo = (const float*)d_in[4];
    float* out = (float*)d_out;

    float *qp, *kp, *vp, *ap, *xr, *wq, *wk, *wv, *wo;
    cudaGetSymbolAddress((void**)&qp, g_q);
    cudaGetSymbolAddress((void**)&kp, g_k);
    cudaGetSymbolAddress((void**)&vp, g_v);
    cudaGetSymbolAddress((void**)&ap, g_attn);
    cudaGetSymbolAddress((void**)&xr, g_xr);
    cudaGetSymbolAddress((void**)&wq, g_wq);
    cudaGetSymbolAddress((void**)&wk, g_wk);
    cudaGetSymbolAddress((void**)&wv, g_wv);
    cudaGetSymbolAddress((void**)&wo, g_wo);

    cudaFuncSetAttribute((const void*)tf32_gemm,
                         cudaFuncAttributeMaxDynamicSharedMemorySize, G_SMEM);
    cudaFuncSetAttribute((const void*)flash_attn_tc,
                         cudaFuncAttributeMaxDynamicSharedMemorySize, FA2_SMEM);

    // Round GEMM operands to nearest-tf32
    int n4x = BT_ * C_ / 4, n4w = C_ * C_ / 4;
    tf32_round_kernel<<<n4x / 256, 256>>>((const float4*)x,  (float4*)xr, n4x);
    tf32_round_kernel<<<n4w / 256, 256>>>((const float4*)Wq, (float4*)wq, n4w);
    tf32_round_kernel<<<n4w / 256, 256>>>((const float4*)Wk, (float4*)wk, n4w);
    tf32_round_kernel<<<n4w / 256, 256>>>((const float4*)Wv, (float4*)wv, n4w);
    tf32_round_kernel<<<n4w / 256, 256>>>((const float4*)Wo, (float4*)wo, n4w);

    dim3 gg(C_ / 128, BT_ / 128);   // (8, 32)
    tf32_gemm<<<gg, 256, G_SMEM>>>(xr, wq, qp, BT_, C_, C_, 0);
    tf32_gemm<<<gg, 256, G_SMEM>>>(xr, wk, kp, BT_, C_, C_, 0);
    tf32_gemm<<<gg, 256, G_SMEM>>>(xr, wv, vp, BT_, C_, C_, 1);  // V rounded

    rope_kernel<<<(B_ * T_ * H_ * (D_ / 2)) / 256, 256>>>(qp, kp);

    flash_attn_tc<<<dim3(T_ / 128, B_ * H_), 256, FA2_SMEM>>>(qp, kp, vp, ap);

    tf32_gemm<<<gg, 256, G_SMEM>>>(ap, wo, out, BT_, C_, C_, 0);
}